// round 2
// baseline (speedup 1.0000x reference)
#include <cuda_runtime.h>
#include <math.h>

#define ROWS 4096
#define COLS 32000
#define NVEC (COLS / 4)        // 8000 float4 per row
#define TPB  256

__device__ float g_row_loss[ROWS];

__global__ __launch_bounds__(TPB) void focal_row_kernel(
    const float* __restrict__ inp,
    const int* __restrict__ tgt_words,   // raw 32-bit view of target buffer
    const float* __restrict__ weight,
    const unsigned* __restrict__ gamma_words)  // may be null
{
    const int row = blockIdx.x;
    const float4* __restrict__ x4 =
        reinterpret_cast<const float4*>(inp + (size_t)row * COLS);

    float sum = 0.0f;
    float m = -INFINITY;
    int   midx = 0;

    for (int i = threadIdx.x; i < NVEC; i += TPB) {
        float4 v = x4[i];
        sum += __expf(v.x);
        sum += __expf(v.y);
        sum += __expf(v.z);
        sum += __expf(v.w);
        int base = i << 2;
        if (v.x > m) { m = v.x; midx = base;     }
        if (v.y > m) { m = v.y; midx = base + 1; }
        if (v.z > m) { m = v.z; midx = base + 2; }
        if (v.w > m) { m = v.w; midx = base + 3; }
    }

    __shared__ float s_sum[TPB];
    __shared__ float s_max[TPB];
    __shared__ int   s_idx[TPB];

    s_sum[threadIdx.x] = sum;
    s_max[threadIdx.x] = m;
    s_idx[threadIdx.x] = midx;
    __syncthreads();

    for (int off = TPB / 2; off > 0; off >>= 1) {
        if (threadIdx.x < off) {
            s_sum[threadIdx.x] += s_sum[threadIdx.x + off];
            float mo = s_max[threadIdx.x + off];
            int   io = s_idx[threadIdx.x + off];
            float mi = s_max[threadIdx.x];
            int   ii = s_idx[threadIdx.x];
            if (mo > mi || (mo == mi && io < ii)) {
                s_max[threadIdx.x] = mo;
                s_idx[threadIdx.x] = io;
            }
        }
        __syncthreads();
    }

    if (threadIdx.x == 0) {
        // --- target dtype detection: int64 layout has zero high words ---
        int odd_or = 0;
        #pragma unroll
        for (int j = 1; j < 64; j += 2) odd_or |= tgt_words[j];
        bool is64 = (odd_or == 0);
        int t = is64 ? tgt_words[2 * row] : tgt_words[row];
        if (t < 0) t = 0;
        if (t >= COLS) t = COLS - 1;

        // --- gamma dtype detection (fp32 vs fp64), default 2.0 ---
        float g = 2.0f;
        if (gamma_words) {
            float f0 = __uint_as_float(gamma_words[0]);
            if (isfinite(f0) && f0 > 0.0f && f0 < 1.0e6f) {
                g = f0;
            } else {
                unsigned long long bits =
                    ((unsigned long long)gamma_words[1] << 32) | gamma_words[0];
                double d = __longlong_as_double((long long)bits);
                if (isfinite(d) && d > 0.0 && d < 1.0e6) g = (float)d;
            }
        }

        float lse   = logf(s_sum[0]);
        float xt    = inp[(size_t)row * COLS + (size_t)t];
        float logpt = xt - lse;          // log p_t
        float pt    = expf(logpt);
        float w     = weight[s_idx[0]];
        g_row_loss[row] = w * powf(1.0f - pt, g) * (-logpt);
    }
}

__global__ __launch_bounds__(1024) void focal_reduce_kernel(float* __restrict__ out)
{
    __shared__ float s[1024];
    float v = 0.0f;
    for (int i = threadIdx.x; i < ROWS; i += 1024) v += g_row_loss[i];
    s[threadIdx.x] = v;
    __syncthreads();
    for (int off = 512; off > 0; off >>= 1) {
        if (threadIdx.x < off) s[threadIdx.x] += s[threadIdx.x + off];
        __syncthreads();
    }
    if (threadIdx.x == 0) out[0] = s[0];
}

extern "C" void kernel_launch(void* const* d_in, const int* in_sizes, int n_in,
                              void* d_out, int out_size)
{
    // Identify buffers by element count (mutually distinct for this problem):
    //   input  : ROWS*COLS = 131,072,000
    //   weight : COLS      = 32,000
    //   target : ROWS      = 4,096
    //   gamma  : 1 (scalar, may be absent)
    const float*    inp    = nullptr;
    const int*      tgtw   = nullptr;
    const float*    weight = nullptr;
    const unsigned* gammaw = nullptr;

    for (int i = 0; i < n_in; i++) {
        long long n = in_sizes[i];
        if (n == (long long)ROWS * COLS) inp    = (const float*)d_in[i];
        else if (n == COLS)              weight = (const float*)d_in[i];
        else if (n == ROWS)              tgtw   = (const int*)d_in[i];
        else if (n <= 2)                 gammaw = (const unsigned*)d_in[i];
    }

    float* out = (float*)d_out;

    focal_row_kernel<<<ROWS, TPB>>>(inp, tgtw, weight, gammaw);
    focal_reduce_kernel<<<1, 1024>>>(out);
}

// round 3
// speedup vs baseline: 1.0192x; 1.0192x over previous
#include <cuda_runtime.h>
#include <math.h>

#define ROWS 4096
#define COLS 32000
#define NVEC (COLS / 4)        // 8000 float4 per row
#define TPB  320               // 8000 / 320 = 25 iterations exactly, no tail
#define NWARP (TPB / 32)       // 10

__device__ unsigned long long g_acc  = 0ULL;   // fixed-point (2^32) loss accumulator
__device__ unsigned int       g_done = 0u;     // completed-block counter

__global__ __launch_bounds__(TPB) void focal_kernel(
    const float* __restrict__ inp,
    const int* __restrict__ tgt_words,          // raw 32-bit view of target buffer
    const float* __restrict__ weight,
    const unsigned* __restrict__ gamma_words,   // may be null
    float* __restrict__ out)
{
    const int row = blockIdx.x;
    const float4* __restrict__ x4 =
        reinterpret_cast<const float4*>(inp + (size_t)row * COLS);

    float s0 = 0.0f, s1 = 0.0f;
    float m = -INFINITY;
    int   midx = 0;

    #pragma unroll 5
    for (int i = threadIdx.x; i < NVEC; i += TPB) {
        float4 v = __ldcs(&x4[i]);
        s0 += __expf(v.x) + __expf(v.y);
        s1 += __expf(v.z) + __expf(v.w);
        float m4 = fmaxf(fmaxf(v.x, v.y), fmaxf(v.z, v.w));
        if (m4 > m) {                         // rare: ~6 hits per thread total
            m = m4;
            int b = i << 2;
            midx = (v.x == m4) ? b
                 : (v.y == m4) ? b + 1
                 : (v.z == m4) ? b + 2
                 :               b + 3;       // first-occurrence within the quad
        }
    }
    float sum = s0 + s1;

    // ---- warp-level reduction: sum, and (max, idx) with min-index tie-break ----
    const unsigned full = 0xFFFFFFFFu;
    #pragma unroll
    for (int off = 16; off > 0; off >>= 1) {
        sum += __shfl_xor_sync(full, sum, off);
        float mo = __shfl_xor_sync(full, m, off);
        int   io = __shfl_xor_sync(full, midx, off);
        if (mo > m || (mo == m && io < midx)) { m = mo; midx = io; }
    }

    __shared__ float sh_sum[NWARP];
    __shared__ float sh_max[NWARP];
    __shared__ int   sh_idx[NWARP];
    int wid = threadIdx.x >> 5, lid = threadIdx.x & 31;
    if (lid == 0) { sh_sum[wid] = sum; sh_max[wid] = m; sh_idx[wid] = midx; }
    __syncthreads();

    if (threadIdx.x == 0) {
        float tsum = sh_sum[0];
        float tm   = sh_max[0];
        int   ti   = sh_idx[0];
        #pragma unroll
        for (int w = 1; w < NWARP; w++) {
            tsum += sh_sum[w];
            if (sh_max[w] > tm || (sh_max[w] == tm && sh_idx[w] < ti)) {
                tm = sh_max[w];
                ti = sh_idx[w];
            }
        }

        // --- target dtype detection: int64 layout has zero high words ---
        int odd_or = 0;
        #pragma unroll
        for (int j = 1; j < 64; j += 2) odd_or |= tgt_words[j];
        int t = (odd_or == 0) ? tgt_words[2 * row] : tgt_words[row];
        t = min(max(t, 0), COLS - 1);

        // --- gamma dtype detection (fp32 vs fp64), default 2.0 ---
        float g = 2.0f;
        if (gamma_words) {
            float f0 = __uint_as_float(gamma_words[0]);
            if (isfinite(f0) && f0 > 0.0f && f0 < 1.0e6f) {
                g = f0;
            } else {
                unsigned long long bits =
                    ((unsigned long long)gamma_words[1] << 32) | gamma_words[0];
                double d = __longlong_as_double((long long)bits);
                if (isfinite(d) && d > 0.0 && d < 1.0e6) g = (float)d;
            }
        }

        float lse   = logf(tsum);
        float xt    = inp[(size_t)row * COLS + (size_t)t];
        float logpt = xt - lse;               // log p_t  (always < 0)
        float pt    = expf(logpt);
        float w     = weight[ti];
        float loss  = w * powf(1.0f - pt, g) * (-logpt);

        // ---- deterministic fixed-point accumulation (order-independent) ----
        unsigned long long q =
            (unsigned long long)llrint((double)loss * 4294967296.0);
        atomicAdd(&g_acc, q);
        __threadfence();
        unsigned int done = atomicAdd(&g_done, 1u);
        if (done == gridDim.x - 1) {          // last block finalizes + self-resets
            unsigned long long total = atomicExch(&g_acc, 0ULL);
            out[0] = (float)((double)total * (1.0 / 4294967296.0));
            atomicExch(&g_done, 0u);
        }
    }
}

extern "C" void kernel_launch(void* const* d_in, const int* in_sizes, int n_in,
                              void* d_out, int out_size)
{
    // Identify buffers by element count (mutually distinct for this problem):
    //   input  : ROWS*COLS = 131,072,000
    //   weight : COLS      = 32,000
    //   target : ROWS      = 4,096
    //   gamma  : 1-2 words (scalar, may be absent)
    const float*    inp    = nullptr;
    const int*      tgtw   = nullptr;
    const float*    weight = nullptr;
    const unsigned* gammaw = nullptr;

    for (int i = 0; i < n_in; i++) {
        long long n = in_sizes[i];
        if (n == (long long)ROWS * COLS) inp    = (const float*)d_in[i];
        else if (n == COLS)              weight = (const float*)d_in[i];
        else if (n == ROWS)              tgtw   = (const int*)d_in[i];
        else if (n <= 2)                 gammaw = (const unsigned*)d_in[i];
    }

    float* out = (float*)d_out;

    focal_kernel<<<ROWS, TPB>>>(inp, tgtw, weight, gammaw, out);
}